// round 14
// baseline (speedup 1.0000x reference)
#include <cuda_runtime.h>
#include <cstdint>

// Problem constants (established world: int32 inputs, float32 output).
#define BATCH 1024
#define TLEN  4096
#define NNEUR 4096
#define NB    16
#define WPN   2115          // ceil(65536/31)

#define SZ_X    4194304
#define SZ_CONN 65536
#define SZ_MEM  8663040

// Packed x, batch-major uint16: PX16[bt][t], bt = batch tile of 16
// (64 tiles), t = 0..4095. Bit b of PX16[bt*4096+t] = x[bt*16+b][t] & 1.
__device__ __align__(16) uint16_t PX16[64 * 4096];

// ---------------------------------------------------------------------------
// Pack kernel: one thread per packed 16-bit word (262144 threads).
// Loads coalesced across lanes (consecutive t for fixed b).
// ---------------------------------------------------------------------------
__global__ void pack_kernel(const int* __restrict__ x) {
    int idx = blockIdx.x * blockDim.x + threadIdx.x;   // 0 .. 262143
    int bt = idx >> 12;          // batch tile (0..63)
    int t  = idx & 4095;
    const int* xb = x + (size_t)bt * 16 * TLEN + t;
    uint32_t w = 0;
#pragma unroll
    for (int b = 0; b < 16; b++)
        w |= ((uint32_t)xb[b * TLEN] & 1u) << b;
    PX16[idx] = (uint16_t)w;
}

// 8x8 bit-matrix transpose (Hacker's Delight).
__device__ __forceinline__ unsigned long long tr8(unsigned long long x) {
    unsigned long long t;
    t = (x ^ (x >> 7))  & 0x00AA00AA00AA00AAull; x = x ^ t ^ (t << 7);
    t = (x ^ (x >> 14)) & 0x0000CCCC0000CCCCull; x = x ^ t ^ (t << 14);
    t = (x ^ (x >> 28)) & 0x00000000F0F0F0F0ull; x = x ^ t ^ (t << 28);
    return x;
}

// ---------------------------------------------------------------------------
// Lookup, occupancy-optimized: batch tile of 16 halves the per-thread
// working set (v[16] dies early; pk[8] + w[16] live) -> ~48 regs ->
// 10 blocks/SM = 40 warps (vs 28 before) for latency hiding.
// Grid (32, 64) = 2048 blocks; 128 lanes = 128 consecutive neurons.
// ---------------------------------------------------------------------------
__global__ void __launch_bounds__(128, 10)
lookup_kernel(const int* __restrict__ conn,
              const int* __restrict__ mem,
              float*     __restrict__ out) {
    __shared__ __align__(16) uint16_t sx[4096];   // 8 KB tile

    const int n  = blockIdx.x * 128 + threadIdx.x;
    const int b0 = blockIdx.y * 16;               // batch-tile base

    // Cooperative load of the packed-x tile (8 KB = 512 uint4).
    {
        const uint4* src = reinterpret_cast<const uint4*>(PX16 + blockIdx.y * 4096);
        uint4* dst = reinterpret_cast<uint4*>(sx);
#pragma unroll
        for (int r = 0; r < 4; r++)
            dst[threadIdx.x + r * 128] = src[threadIdx.x + r * 128];
    }
    __syncthreads();

    // One LDS.U16 per connection: v[j] bit b = x[b0+b][conn[n][j]].
    uint32_t v[NB];
#pragma unroll
    for (int j = 0; j < NB; j++)
        v[j] = (uint32_t)sx[(uint32_t)conn[n * NB + j]];

    // Phase 1: all 16 addresses, packed 2x16-bit into pk[8].
    // pk[bs*4+p] = addr(batch bs*8+2p) | addr(batch bs*8+2p+1) << 16.
    uint32_t pk[8];
#pragma unroll
    for (int bs = 0; bs < 2; bs++) {              // 8-batch subgroup (byte bs)
        const uint32_t selb = (uint32_t)bs | ((4u + (uint32_t)bs) << 4);

        uint32_t a_lo = __byte_perm(__byte_perm(v[7],  v[6],  selb),
                                    __byte_perm(v[5],  v[4],  selb), 0x5410);
        uint32_t a_hi = __byte_perm(__byte_perm(v[3],  v[2],  selb),
                                    __byte_perm(v[1],  v[0],  selb), 0x5410);
        uint32_t c_lo = __byte_perm(__byte_perm(v[15], v[14], selb),
                                    __byte_perm(v[13], v[12], selb), 0x5410);
        uint32_t c_hi = __byte_perm(__byte_perm(v[11], v[10], selb),
                                    __byte_perm(v[9],  v[8],  selb), 0x5410);

        unsigned long long A  = ((unsigned long long)a_hi << 32) | a_lo;
        unsigned long long Bm = ((unsigned long long)c_hi << 32) | c_lo;
        A  = tr8(A);    // byte k = addr bits 15..8 for batch (bs*8 + k)
        Bm = tr8(Bm);   // byte k = addr bits  7..0 for batch (bs*8 + k)

        const uint32_t Ao0 = (uint32_t)A,  Ao1 = (uint32_t)(A >> 32);
        const uint32_t Bo0 = (uint32_t)Bm, Bo1 = (uint32_t)(Bm >> 32);

        pk[bs * 4 + 0] = __byte_perm(Bo0, Ao0, 0x5140);
        pk[bs * 4 + 1] = __byte_perm(Bo0, Ao0, 0x7362);
        pk[bs * 4 + 2] = __byte_perm(Bo1, Ao1, 0x5140);
        pk[bs * 4 + 3] = __byte_perm(Bo1, Ao1, 0x7362);
    }

    const int* mrow = mem + (size_t)n * WPN;

    // Phase 2: one 16-wide predicated gather batch (int32 world:
    // addr%31 >= 16 -> cell deterministically 0, skip the load).
    uint32_t w[16];
#pragma unroll
    for (int i = 0; i < 16; i++) {
        unsigned a  = (pk[i >> 1] >> ((i & 1) * 16)) & 0xFFFFu;
        unsigned q  = a / 31u;
        unsigned rr = a - q * 31u;
        w[i] = 0u;
        if (rr < 16u)
            w[i] = (uint32_t)__ldg(mrow + q);
    }

    // Extract + coalesced float stores (q/rr recomputed: 2 ALU each).
#pragma unroll
    for (int i = 0; i < 16; i++) {
        unsigned a  = (pk[i >> 1] >> ((i & 1) * 16)) & 0xFFFFu;
        unsigned q  = a / 31u;
        unsigned rr = a - q * 31u;
        unsigned cell = (w[i] >> (2u * rr)) & 3u;
        out[(size_t)(b0 + i) * NNEUR + n] = (float)cell;
    }
}

// ---------------------------------------------------------------------------
extern "C" void kernel_launch(void* const* d_in, const int* in_sizes, int n_in,
                              void* d_out, int out_size) {
    const void* x    = nullptr;
    const void* conn = nullptr;
    const void* mem  = nullptr;
    for (int i = 0; i < n_in; i++) {
        if      (in_sizes[i] == SZ_X)    x    = d_in[i];
        else if (in_sizes[i] == SZ_CONN) conn = d_in[i];
        else if (in_sizes[i] == SZ_MEM)  mem  = d_in[i];
    }
    if (!x || !conn || !mem) { x = d_in[0]; conn = d_in[1]; mem = d_in[2]; }

    pack_kernel<<<1024, 256>>>((const int*)x);
    lookup_kernel<<<dim3(NNEUR / 128, BATCH / 16), 128>>>(
        (const int*)conn, (const int*)mem, (float*)d_out);
}

// round 15
// speedup vs baseline: 1.0446x; 1.0446x over previous
#include <cuda_runtime.h>
#include <cstdint>

// Problem constants (established world: int32 inputs, float32 output).
#define BATCH 1024
#define TLEN  4096
#define NNEUR 4096
#define NB    16
#define WPN   2115          // ceil(65536/31)

#define SZ_X    4194304
#define SZ_CONN 65536
#define SZ_MEM  8663040

#define NPB   8             // neurons per block
#define THR   256

// Packed x, COLUMN-major: XC[t*32 + w], bit j = x[w*32 + j][t] & 1.
// One column t = 32 consecutive words = 128B (one cache line).
__device__ __align__(16) uint32_t XC[4096 * 32];

// ---------------------------------------------------------------------------
// Pack kernel: thread per (w, t); x reads coalesced (lanes = consecutive t),
// writes scattered (1 wf each -- negligible, 131K total).
// ---------------------------------------------------------------------------
__global__ void pack_kernel(const int* __restrict__ x) {
    int idx = blockIdx.x * blockDim.x + threadIdx.x;   // 0 .. 131071
    int w = idx >> 12;           // batch word (0..31)
    int t = idx & 4095;
    const int* xb = x + (size_t)w * 32 * TLEN + t;
    uint32_t v = 0;
#pragma unroll
    for (int j = 0; j < 32; j++)
        v |= ((uint32_t)xb[j * TLEN] & 1u) << j;
    XC[t * 32 + w] = v;
}

// 8x8 bit-matrix transpose (Hacker's Delight).
__device__ __forceinline__ unsigned long long tr8(unsigned long long x) {
    unsigned long long t;
    t = (x ^ (x >> 7))  & 0x00AA00AA00AA00AAull; x = x ^ t ^ (t << 7);
    t = (x ^ (x >> 14)) & 0x0000CCCC0000CCCCull; x = x ^ t ^ (t << 14);
    t = (x ^ (x >> 28)) & 0x00000000F0F0F0F0ull; x = x ^ t ^ (t << 28);
    return x;
}

// smem layout (bytes): rows [0, 67680), xcols [67680, 84576), conn [84576, 85088)
#define SM_ROWS_W   (NPB * WPN)          // 16920 words
#define SM_XC_OFF   (SM_ROWS_W)          // word offset of xcols
#define SM_XC_STR   33                   // padded column stride (words)
#define SM_CONN_OFF (SM_XC_OFF + 128 * SM_XC_STR)
#define SM_TOTAL_B  ((SM_CONN_OFF + 128) * 4)

// ---------------------------------------------------------------------------
// Lookup: block = 8 neurons x ALL 1024 batches. The 8 memory rows live in
// SHARED (bulk coalesced load) -> every gather is an LDS, not an L2 miss.
// Thread = (ng = tid&7, w = tid>>3): neuron ng, 32 batches [w*32, w*32+32).
// Warp = 8 consecutive neurons x 4 words -> stores = 4x32B sectors/inst.
// ---------------------------------------------------------------------------
__global__ void __launch_bounds__(THR, 2)
lookup_kernel(const int* __restrict__ conn,
              const int* __restrict__ mem,
              float*     __restrict__ out) {
    extern __shared__ __align__(16) uint32_t sm[];

    const int tid = threadIdx.x;
    const int n0  = blockIdx.x * NPB;

    // Phase A1: bulk-load 8 memory rows (contiguous 67680B) as uint4.
    {
        const uint4* src = reinterpret_cast<const uint4*>(mem + (size_t)n0 * WPN);
        uint4* dst = reinterpret_cast<uint4*>(sm);
        const int nvec = SM_ROWS_W / 4;                 // 4230
#pragma unroll
        for (int r = 0; r < 16; r++)
            dst[tid + r * THR] = src[tid + r * THR];
        if (tid < nvec - 16 * THR)                      // 134 remainder
            dst[tid + 16 * THR] = src[tid + 16 * THR];
    }

    // Phase A2: conn tile (128 consecutive ints).
    if (tid < 128)
        sm[SM_CONN_OFF + tid] = (uint32_t)conn[n0 * NB + tid];
    __syncthreads();   // conn visible before column gather

    // Phase A3: gather the 128 needed x-columns (each = 128B line).
    {
        const int wid  = tid >> 5;
        const int lane = tid & 31;
        for (int c = wid; c < 128; c += 8) {
            uint32_t t = sm[SM_CONN_OFF + c];
            sm[SM_XC_OFF + c * SM_XC_STR + lane] = XC[t * 32 + lane];
        }
    }
    __syncthreads();

    const int ng = tid & 7;          // neuron within block
    const int w  = tid >> 3;         // 32-batch word (0..31)
    const uint32_t* srow = sm + ng * WPN;

    // x words for this thread's 32 batches, all 16 connections.
    uint32_t v[NB];
#pragma unroll
    for (int j = 0; j < NB; j++)
        v[j] = sm[SM_XC_OFF + (ng * NB + j) * SM_XC_STR + w];

    const int nn = n0 + ng;

#pragma unroll
    for (int sb = 0; sb < 4; sb++) {           // 8-batch subgroup (byte sb)
        const uint32_t selb = (uint32_t)sb | ((4u + (uint32_t)sb) << 4);

        uint32_t a_lo = __byte_perm(__byte_perm(v[7],  v[6],  selb),
                                    __byte_perm(v[5],  v[4],  selb), 0x5410);
        uint32_t a_hi = __byte_perm(__byte_perm(v[3],  v[2],  selb),
                                    __byte_perm(v[1],  v[0],  selb), 0x5410);
        uint32_t c_lo = __byte_perm(__byte_perm(v[15], v[14], selb),
                                    __byte_perm(v[13], v[12], selb), 0x5410);
        uint32_t c_hi = __byte_perm(__byte_perm(v[11], v[10], selb),
                                    __byte_perm(v[9],  v[8],  selb), 0x5410);

        unsigned long long A  = ((unsigned long long)a_hi << 32) | a_lo;
        unsigned long long Bm = ((unsigned long long)c_hi << 32) | c_lo;
        A  = tr8(A);    // byte k = addr bits 15..8 for batch (w*32 + sb*8 + k)
        Bm = tr8(Bm);   // byte k = addr bits  7..0

        const uint32_t Ao0 = (uint32_t)A,  Ao1 = (uint32_t)(A >> 32);
        const uint32_t Bo0 = (uint32_t)Bm, Bo1 = (uint32_t)(Bm >> 32);

        uint32_t pk[4];
        pk[0] = __byte_perm(Bo0, Ao0, 0x5140);
        pk[1] = __byte_perm(Bo0, Ao0, 0x7362);
        pk[2] = __byte_perm(Bo1, Ao1, 0x5140);
        pk[3] = __byte_perm(Bo1, Ao1, 0x7362);

        // 8 gathers from the smem-resident row + extract + store.
        const int b0 = w * 32 + sb * 8;
#pragma unroll
        for (int i = 0; i < 8; i++) {
            unsigned a  = (pk[i >> 1] >> ((i & 1) * 16)) & 0xFFFFu;
            unsigned q  = a / 31u;
            unsigned rr = a - q * 31u;
            uint32_t wd = 0u;
            if (rr < 16u)                       // int32 world: else cell = 0
                wd = srow[q];
            unsigned cell = (wd >> (2u * rr)) & 3u;
            out[(size_t)(b0 + i) * NNEUR + nn] = (float)cell;
        }
    }
}

// ---------------------------------------------------------------------------
extern "C" void kernel_launch(void* const* d_in, const int* in_sizes, int n_in,
                              void* d_out, int out_size) {
    const void* x    = nullptr;
    const void* conn = nullptr;
    const void* mem  = nullptr;
    for (int i = 0; i < n_in; i++) {
        if      (in_sizes[i] == SZ_X)    x    = d_in[i];
        else if (in_sizes[i] == SZ_CONN) conn = d_in[i];
        else if (in_sizes[i] == SZ_MEM)  mem  = d_in[i];
    }
    if (!x || !conn || !mem) { x = d_in[0]; conn = d_in[1]; mem = d_in[2]; }

    static int smem_set = 0;
    if (!smem_set) {
        cudaFuncSetAttribute(lookup_kernel,
                             cudaFuncAttributeMaxDynamicSharedMemorySize,
                             SM_TOTAL_B);
        smem_set = 1;
    }

    pack_kernel<<<512, 256>>>((const int*)x);
    lookup_kernel<<<NNEUR / NPB, THR, SM_TOTAL_B>>>(
        (const int*)conn, (const int*)mem, (float*)d_out);
}

// round 16
// speedup vs baseline: 1.1391x; 1.0904x over previous
#include <cuda_runtime.h>
#include <cstdint>

// Problem constants (established world: int32 inputs, float32 output).
#define BATCH 1024
#define TLEN  4096
#define NNEUR 4096
#define NB    16
#define WPN   2115          // ceil(65536/31)

#define SZ_X    4194304
#define SZ_CONN 65536
#define SZ_MEM  8663040

#define NPB   8             // neurons per block
#define THR   512

// Packed x, COLUMN-major: XC[t*32 + w], bit j = x[w*32 + j][t] & 1.
__device__ __align__(16) uint32_t XC[4096 * 32];

__global__ void pack_kernel(const int* __restrict__ x) {
    int idx = blockIdx.x * blockDim.x + threadIdx.x;   // 0 .. 131071
    int w = idx >> 12;           // batch word (0..31)
    int t = idx & 4095;
    const int* xb = x + (size_t)w * 32 * TLEN + t;
    uint32_t v = 0;
#pragma unroll
    for (int j = 0; j < 32; j++)
        v |= ((uint32_t)xb[j * TLEN] & 1u) << j;
    XC[t * 32 + w] = v;
}

// 8x8 bit-matrix transpose (Hacker's Delight).
__device__ __forceinline__ unsigned long long tr8(unsigned long long x) {
    unsigned long long t;
    t = (x ^ (x >> 7))  & 0x00AA00AA00AA00AAull; x = x ^ t ^ (t << 7);
    t = (x ^ (x >> 14)) & 0x0000CCCC0000CCCCull; x = x ^ t ^ (t << 14);
    t = (x ^ (x >> 28)) & 0x00000000F0F0F0F0ull; x = x ^ t ^ (t << 28);
    return x;
}

// smem layout (words): rows [0, 16920), xcols [16920, +128*33), conn [.., +128)
#define SM_ROWS_W   (NPB * WPN)          // 16920 words
#define SM_XC_OFF   (SM_ROWS_W)
#define SM_XC_STR   33                   // padded column stride (words)
#define SM_CONN_OFF (SM_XC_OFF + 128 * SM_XC_STR)
#define SM_TOTAL_B  ((SM_CONN_OFF + 128) * 4)

// ---------------------------------------------------------------------------
// Lookup: block = 8 neurons x ALL 1024 batches, memory rows in SHARED.
// THR=512: thread = (ng = tid&7, w = (tid>>3)&31, half = tid>>8) handling
// 16 batches (subgroups sb = 2*half, 2*half+1). Identical per-output work
// to the 256-thread version, but 32 warps/SM instead of 16 -> latency
// exposure (the proven binder) halves.
// ---------------------------------------------------------------------------
__global__ void __launch_bounds__(THR, 2)
lookup_kernel(const int* __restrict__ conn,
              const int* __restrict__ mem,
              float*     __restrict__ out) {
    extern __shared__ __align__(16) uint32_t sm[];

    const int tid = threadIdx.x;
    const int n0  = blockIdx.x * NPB;

    // Phase A1: bulk-load 8 memory rows (67680 B) as uint4.
    {
        const uint4* src = reinterpret_cast<const uint4*>(mem + (size_t)n0 * WPN);
        uint4* dst = reinterpret_cast<uint4*>(sm);
        const int nvec = SM_ROWS_W / 4;                 // 4230
#pragma unroll
        for (int r = 0; r < 8; r++)
            dst[tid + r * THR] = src[tid + r * THR];
        if (tid < nvec - 8 * THR)                       // 134 remainder
            dst[tid + 8 * THR] = src[tid + 8 * THR];
    }

    // Phase A2: conn tile (128 consecutive ints).
    if (tid < 128)
        sm[SM_CONN_OFF + tid] = (uint32_t)conn[n0 * NB + tid];
    __syncthreads();

    // Phase A3: gather the 128 needed x-columns (each 128B line).
    {
        const int wid  = tid >> 5;      // 16 warps
        const int lane = tid & 31;
        for (int c = wid; c < 128; c += 16) {
            uint32_t t = sm[SM_CONN_OFF + c];
            sm[SM_XC_OFF + c * SM_XC_STR + lane] = XC[t * 32 + lane];
        }
    }
    __syncthreads();

    const int ng   = tid & 7;           // neuron within block
    const int w    = (tid >> 3) & 31;   // 32-batch word
    const int half = tid >> 8;          // 0 or 1 -> bytes {0,1} or {2,3}
    const uint32_t* srow = sm + ng * WPN;

    // x words for this thread's batches (same word serves both halves).
    uint32_t v[NB];
#pragma unroll
    for (int j = 0; j < NB; j++)
        v[j] = sm[SM_XC_OFF + (ng * NB + j) * SM_XC_STR + w];

    // Addresses for 2 subgroups -> pk[8].
    uint32_t pk[8];
#pragma unroll
    for (int s = 0; s < 2; s++) {
        const uint32_t sb = (uint32_t)(half * 2 + s);   // byte index 0..3
        const uint32_t selb = sb | ((4u + sb) << 4);

        uint32_t a_lo = __byte_perm(__byte_perm(v[7],  v[6],  selb),
                                    __byte_perm(v[5],  v[4],  selb), 0x5410);
        uint32_t a_hi = __byte_perm(__byte_perm(v[3],  v[2],  selb),
                                    __byte_perm(v[1],  v[0],  selb), 0x5410);
        uint32_t c_lo = __byte_perm(__byte_perm(v[15], v[14], selb),
                                    __byte_perm(v[13], v[12], selb), 0x5410);
        uint32_t c_hi = __byte_perm(__byte_perm(v[11], v[10], selb),
                                    __byte_perm(v[9],  v[8],  selb), 0x5410);

        unsigned long long A  = ((unsigned long long)a_hi << 32) | a_lo;
        unsigned long long Bm = ((unsigned long long)c_hi << 32) | c_lo;
        A  = tr8(A);
        Bm = tr8(Bm);

        const uint32_t Ao0 = (uint32_t)A,  Ao1 = (uint32_t)(A >> 32);
        const uint32_t Bo0 = (uint32_t)Bm, Bo1 = (uint32_t)(Bm >> 32);

        pk[s * 4 + 0] = __byte_perm(Bo0, Ao0, 0x5140);
        pk[s * 4 + 1] = __byte_perm(Bo0, Ao0, 0x7362);
        pk[s * 4 + 2] = __byte_perm(Bo1, Ao1, 0x5140);
        pk[s * 4 + 3] = __byte_perm(Bo1, Ao1, 0x7362);
    }

    // 16 predicated smem gathers, batched for MLP.
    uint32_t wv[16];
#pragma unroll
    for (int i = 0; i < 16; i++) {
        unsigned a  = (pk[i >> 1] >> ((i & 1) * 16)) & 0xFFFFu;
        unsigned q  = a / 31u;
        unsigned rr = a - q * 31u;
        wv[i] = 0u;
        if (rr < 16u)                   // int32 world: else cell = 0
            wv[i] = srow[q];
    }

    // Extract + store.
    const int nn = n0 + ng;
    const int bbase = w * 32 + half * 16;
#pragma unroll
    for (int i = 0; i < 16; i++) {
        unsigned a  = (pk[i >> 1] >> ((i & 1) * 16)) & 0xFFFFu;
        unsigned q  = a / 31u;
        unsigned rr = a - q * 31u;
        unsigned cell = (wv[i] >> (2u * rr)) & 3u;
        out[(size_t)(bbase + i) * NNEUR + nn] = (float)cell;
    }
}

// ---------------------------------------------------------------------------
extern "C" void kernel_launch(void* const* d_in, const int* in_sizes, int n_in,
                              void* d_out, int out_size) {
    const void* x    = nullptr;
    const void* conn = nullptr;
    const void* mem  = nullptr;
    for (int i = 0; i < n_in; i++) {
        if      (in_sizes[i] == SZ_X)    x    = d_in[i];
        else if (in_sizes[i] == SZ_CONN) conn = d_in[i];
        else if (in_sizes[i] == SZ_MEM)  mem  = d_in[i];
    }
    if (!x || !conn || !mem) { x = d_in[0]; conn = d_in[1]; mem = d_in[2]; }

    static int smem_set = 0;
    if (!smem_set) {
        cudaFuncSetAttribute(lookup_kernel,
                             cudaFuncAttributeMaxDynamicSharedMemorySize,
                             SM_TOTAL_B);
        smem_set = 1;
    }

    pack_kernel<<<512, 256>>>((const int*)x);
    lookup_kernel<<<NNEUR / NPB, THR, SM_TOTAL_B>>>(
        (const int*)conn, (const int*)mem, (float*)d_out);
}